// round 15
// baseline (speedup 1.0000x reference)
#include <cuda_runtime.h>
#include <cuda_fp16.h>

#define NN   100000
#define EE   3200000
#define KORD 10
#define CC   64
#define FIN  512

// ---------------- scratch (static __device__, per allocation rules) -------------
// d_deg is zero at module load; k_scan3 re-zeroes it after use so every
// kernel_launch call sees it zeroed (invariant maintained across graph replays).
__device__ int     d_deg[NN];
__device__ int     d_rowptr[NN + 1];
__device__ int     d_cursor[NN];
__device__ int     d_blk[128];
__device__ float   d_dinv[NN];              // deg>0 ? rsqrt(deg) : 1
__device__ float   d_wi[NN];                // dinv^2
__device__ float   d_sdeg[NN];              // sqrt(deg) or 1
__device__ int     d_srcs[EE];
__device__ __half2 d_Ph[3][NN * (CC / 2)];  // rotating Chebyshev buffers, R_n = dinv*P_n
__device__ float   d_acc[NN * CC];          // weighted combine accumulator (fp32)

// ---------------- CSR build ----------------------------------------------------
__global__ void k_count(const int* __restrict__ ei) {
    int t = blockIdx.x * blockDim.x + threadIdx.x;
    if (t < EE / 4) {
        int4 c4 = ((const int4*)(ei + EE))[t];
        atomicAdd(&d_deg[c4.x], 1);
        atomicAdd(&d_deg[c4.y], 1);
        atomicAdd(&d_deg[c4.z], 1);
        atomicAdd(&d_deg[c4.w], 1);
    }
}

__global__ void k_scan1() {
    __shared__ int sh[1024];
    int i = blockIdx.x * 1024 + threadIdx.x;
    int v = (i < NN) ? d_deg[i] : 0;
    sh[threadIdx.x] = v;
    __syncthreads();
    for (int off = 1; off < 1024; off <<= 1) {
        int t = (threadIdx.x >= off) ? sh[threadIdx.x - off] : 0;
        __syncthreads();
        sh[threadIdx.x] += t;
        __syncthreads();
    }
    if (i < NN) d_rowptr[i] = sh[threadIdx.x] - v;     // block-local exclusive
    if (threadIdx.x == 1023) d_blk[blockIdx.x] = sh[1023];
}

__global__ void k_scan2(int nblk) {                    // parallel exclusive scan, nblk<=128
    __shared__ int sh[128];
    int t = threadIdx.x;
    int v = (t < nblk) ? d_blk[t] : 0;
    sh[t] = v;
    __syncthreads();
    for (int off = 1; off < 128; off <<= 1) {
        int u = (t >= off) ? sh[t - off] : 0;
        __syncthreads();
        sh[t] += u;
        __syncthreads();
    }
    if (t < nblk) d_blk[t] = sh[t] - v;
}

__global__ void k_scan3() {
    int i = blockIdx.x * blockDim.x + threadIdx.x;
    if (i < NN) {
        int rp = d_rowptr[i] + d_blk[i >> 10];
        d_rowptr[i] = rp;
        d_cursor[i] = rp;
        int dg = d_deg[i];
        d_deg[i] = 0;                       // restore invariant for next launch
        d_dinv[i] = (dg > 0) ? rsqrtf((float)dg) : 1.0f;
        d_wi[i]   = (dg > 0) ? (1.0f / (float)dg) : 1.0f;
        d_sdeg[i] = (dg > 0) ? sqrtf((float)dg) : 1.0f;
    }
    if (i == 0) d_rowptr[NN] = EE;
}

__global__ void k_scatter(const int* __restrict__ ei) {
    int t = blockIdx.x * blockDim.x + threadIdx.x;
    if (t < EE / 4) {
        int4 r4 = ((const int4*)ei)[t];
        int4 c4 = ((const int4*)(ei + EE))[t];
        int p;
        p = atomicAdd(&d_cursor[c4.x], 1); d_srcs[p] = r4.x;
        p = atomicAdd(&d_cursor[c4.y], 1); d_srcs[p] = r4.y;
        p = atomicAdd(&d_cursor[c4.z], 1); d_srcs[p] = r4.z;
        p = atomicAdd(&d_cursor[c4.w], 1); d_srcs[p] = r4.w;
    }
}

// ---------------- GEMM: h = x @ W + b (fp32 float4, 128x64 tile, 8x4 micro) -----
// 256 threads as 16x16; each thread computes 8 rows x 4 cols. K-tile 32.
// Epilogue writes fp16 R0 (= dinv*h) and initializes acc with coef0=1 * mfw[0].
__global__ __launch_bounds__(256) void k_gemm(const float* __restrict__ x,
                                              const float* __restrict__ W,
                                              const float* __restrict__ bias,
                                              const float* __restrict__ mfw) {
    __shared__ float xsT[32][132];  // [k][m], padded
    __shared__ float Ws[32][64];    // [k][c]
    int tid = threadIdx.x;
    int m0  = blockIdx.x * 128;
    int ty  = tid >> 4, tx = tid & 15;

    float acc[8][4];
#pragma unroll
    for (int i = 0; i < 8; i++)
#pragma unroll
        for (int j = 0; j < 4; j++) acc[i][j] = 0.f;

    for (int k0 = 0; k0 < FIN; k0 += 32) {
#pragma unroll
        for (int it = 0; it < 4; ++it) {
            int idx = tid + it * 256;
            int row = idx >> 3, fc = idx & 7;
            float4 v = make_float4(0.f, 0.f, 0.f, 0.f);
            int gr = m0 + row;
            if (gr < NN) v = *(const float4*)(x + (long)gr * FIN + k0 + fc * 4);
            xsT[fc * 4 + 0][row] = v.x;
            xsT[fc * 4 + 1][row] = v.y;
            xsT[fc * 4 + 2][row] = v.z;
            xsT[fc * 4 + 3][row] = v.w;
        }
#pragma unroll
        for (int it = 0; it < 2; ++it) {
            int idx = tid + it * 256;
            int kr = idx >> 4, fc = idx & 15;
            *(float4*)&Ws[kr][fc * 4] = *(const float4*)(W + (k0 + kr) * CC + fc * 4);
        }
        __syncthreads();
#pragma unroll
        for (int kk = 0; kk < 32; ++kk) {
            float4 a0 = *(const float4*)&xsT[kk][ty * 8];
            float4 a1 = *(const float4*)&xsT[kk][ty * 8 + 4];
            float4 bb = *(const float4*)&Ws[kk][tx * 4];
            acc[0][0] += a0.x * bb.x; acc[0][1] += a0.x * bb.y; acc[0][2] += a0.x * bb.z; acc[0][3] += a0.x * bb.w;
            acc[1][0] += a0.y * bb.x; acc[1][1] += a0.y * bb.y; acc[1][2] += a0.y * bb.z; acc[1][3] += a0.y * bb.w;
            acc[2][0] += a0.z * bb.x; acc[2][1] += a0.z * bb.y; acc[2][2] += a0.z * bb.z; acc[2][3] += a0.z * bb.w;
            acc[3][0] += a0.w * bb.x; acc[3][1] += a0.w * bb.y; acc[3][2] += a0.w * bb.z; acc[3][3] += a0.w * bb.w;
            acc[4][0] += a1.x * bb.x; acc[4][1] += a1.x * bb.y; acc[4][2] += a1.x * bb.z; acc[4][3] += a1.x * bb.w;
            acc[5][0] += a1.y * bb.x; acc[5][1] += a1.y * bb.y; acc[5][2] += a1.y * bb.z; acc[5][3] += a1.y * bb.w;
            acc[6][0] += a1.z * bb.x; acc[6][1] += a1.z * bb.y; acc[6][2] += a1.z * bb.z; acc[6][3] += a1.z * bb.w;
            acc[7][0] += a1.w * bb.x; acc[7][1] += a1.w * bb.y; acc[7][2] += a1.w * bb.z; acc[7][3] += a1.w * bb.w;
        }
        __syncthreads();
    }

    float4 b4 = *(const float4*)(bias + tx * 4);
    float4 w0 = *(const float4*)(mfw + tx * 4);   // mf_weights[0][c], coef0 = 1
#pragma unroll
    for (int i = 0; i < 8; i++) {
        int row = m0 + ty * 8 + i;
        if (row < NN) {
            float h0 = acc[i][0] + b4.x;
            float h1 = acc[i][1] + b4.y;
            float h2 = acc[i][2] + b4.z;
            float h3 = acc[i][3] + b4.w;
            float dv = d_dinv[row];
            __half2* dst = d_Ph[0] + (long)row * (CC / 2) + tx * 2;
            dst[0] = __floats2half2_rn(dv * h0, dv * h1);   // R0 = dinv * h
            dst[1] = __floats2half2_rn(dv * h2, dv * h3);
            *(float4*)(&d_acc[(long)row * CC + tx * 4]) =
                make_float4(h0 * w0.x, h1 * w0.y, h2 * w0.z, h3 * w0.w);
        }
    }
}

// ---------------- fused propagate + recurrence + weighted accumulate ------------
// Half-warp paired gather: lanes 0-15 read row A, lanes 16-31 read row B, each
// lane loads uint2 (4 halves = cols 4q..4q+3, q = lane&15). One LDG.64 per 2
// edges. Edge chunks of 4 via aligned int4 srcs load; boundary edges clamped
// within the chunk (no extra rows fetched) and their adds predicated off.
// After the loop a single shfl_xor(16) folds the two halves; lanes 0-15 do the
// recurrence, stores, and (final stage) log_softmax with float4/uint2 widths.
__global__ __launch_bounds__(256) void k_prop(int n, int inb, int outb, int pb,
                                              const float* __restrict__ lap,
                                              const float* __restrict__ mfw,
                                              float* __restrict__ out) {
    int gw   = (blockIdx.x * blockDim.x + threadIdx.x) >> 5;
    int lane = threadIdx.x & 31;
    if (gw >= NN) return;
    const char* __restrict__ Pin = (const char*)d_Ph[inb];
    int beg = d_rowptr[gw], end = d_rowptr[gw + 1];
    int half = lane >> 4;        // 0: edges p+half.., 1: ...
    int q    = lane & 15;        // column quad: cols 4q..4q+3, byte offset 8q

    float f0 = 0.f, f1 = 0.f, f2 = 0.f, f3 = 0.f;
    for (int p = beg & ~3; p < end; p += 4) {
        int4 s4 = *(const int4*)&d_srcs[p];          // aligned LDG.128, broadcast
        int eA = p + half;                           // this half's first edge
        int eB = p + 2 + half;                       // this half's second edge
        // clamp within chunk so invalid lanes re-read an in-chunk row
        int eAc = min(max(eA, beg), end - 1) & 3;
        int eBc = min(max(eB, beg), end - 1) & 3;
        int sA = (eAc == 0) ? s4.x : (eAc == 1) ? s4.y : (eAc == 2) ? s4.z : s4.w;
        int sB = (eBc == 0) ? s4.x : (eBc == 1) ? s4.y : (eBc == 2) ? s4.z : s4.w;
        uint2 vA = *(const uint2*)(Pin + (long)sA * 128 + q * 8);
        uint2 vB = *(const uint2*)(Pin + (long)sB * 128 + q * 8);
        if (eA >= beg && eA < end) {
            float2 a = __half22float2(*(const __half2*)&vA.x);
            float2 b = __half22float2(*(const __half2*)&vA.y);
            f0 += a.x; f1 += a.y; f2 += b.x; f3 += b.y;
        }
        if (eB >= beg && eB < end) {
            float2 a = __half22float2(*(const __half2*)&vB.x);
            float2 b = __half22float2(*(const __half2*)&vB.y);
            f0 += a.x; f1 += a.y; f2 += b.x; f3 += b.y;
        }
    }
    // fold the two half-warps (lane L += lane L^16)
    f0 += __shfl_xor_sync(0xffffffffu, f0, 16);
    f1 += __shfl_xor_sync(0xffffffffu, f1, 16);
    f2 += __shfl_xor_sync(0xffffffffu, f2, 16);
    f3 += __shfl_xor_sync(0xffffffffu, f3, 16);

    float w = d_wi[gw];
    float p0, p1, p2, p3;
    if (n >= 2) {
        uint2 qv = *(const uint2*)((const char*)d_Ph[pb] + (long)gw * 128 + q * 8);
        float2 qa = __half22float2(*(const __half2*)&qv.x);
        float2 qb = __half22float2(*(const __half2*)&qv.y);
        p0 = 2.f * w * f0 - qa.x;
        p1 = 2.f * w * f1 - qa.y;
        p2 = 2.f * w * f2 - qb.x;
        p3 = 2.f * w * f3 - qb.y;
    } else {
        p0 = w * f0; p1 = w * f1; p2 = w * f2; p3 = w * f3;
    }

    float sd   = d_sdeg[gw];
    float coef = lap[n - 1];
    float4 mw = *(const float4*)(mfw + n * CC + q * 4);
    float4 a4 = *(const float4*)(d_acc + (long)gw * CC + q * 4);
    a4.x += coef * mw.x * (sd * p0);
    a4.y += coef * mw.y * (sd * p1);
    a4.z += coef * mw.z * (sd * p2);
    a4.w += coef * mw.w * (sd * p3);

    if (n < KORD) {
        if (half == 0) {
            uint2 st;
            *(__half2*)&st.x = __floats2half2_rn(p0, p1);
            *(__half2*)&st.y = __floats2half2_rn(p2, p3);
            *(uint2*)((char*)d_Ph[outb] + (long)gw * 128 + q * 8) = st;
            *(float4*)(d_acc + (long)gw * CC + q * 4) = a4;
        }
    } else {
        // fused log_softmax: reduce over the 16-lane group (cols 4q..4q+3 each)
        float m = fmaxf(fmaxf(a4.x, a4.y), fmaxf(a4.z, a4.w));
#pragma unroll
        for (int o = 8; o; o >>= 1) m = fmaxf(m, __shfl_xor_sync(0xffffffffu, m, o));
        float s = expf(a4.x - m) + expf(a4.y - m) + expf(a4.z - m) + expf(a4.w - m);
#pragma unroll
        for (int o = 8; o; o >>= 1) s += __shfl_xor_sync(0xffffffffu, s, o);
        float l = m + logf(s);
        if (half == 0) {
            *(float4*)(out + (long)gw * CC + q * 4) =
                make_float4(a4.x - l, a4.y - l, a4.z - l, a4.w - l);
        }
    }
}

// ---------------- launch --------------------------------------------------------
extern "C" void kernel_launch(void* const* d_in, const int* in_sizes, int n_in,
                              void* d_out, int out_size) {
    const float* x   = (const float*)d_in[0];
    const int*   ei  = (const int*)d_in[1];     // int32 (JAX default x64-disabled)
    const float* W   = (const float*)d_in[2];
    const float* b   = (const float*)d_in[3];
    const float* lap = (const float*)d_in[4];
    const float* mfw = (const float*)d_in[5];
    float*       out = (float*)d_out;

    (void)in_sizes; (void)n_in; (void)out_size;

    // d_deg is zeroed (module load on call 1; k_scan3 re-zeroes every call)
    k_count<<<(EE / 4 + 255) / 256, 256>>>(ei);
    int nblk = (NN + 1023) / 1024;   // 98
    k_scan1<<<nblk, 1024>>>();
    k_scan2<<<1, 128>>>(nblk);
    k_scan3<<<(NN + 255) / 256, 256>>>();
    k_scatter<<<(EE / 4 + 255) / 256, 256>>>(ei);

    k_gemm<<<(NN + 127) / 128, 256>>>(x, W, b, mfw);

    // warps = NN, 8 warps/block
    int prop_blocks = (NN + 7) / 8;
    for (int n = 1; n <= KORD; n++) {
        int inb  = (n - 1) % 3;
        int outb = n % 3;
        int pb   = (n + 1) % 3;   // == (n-2) mod 3
        k_prop<<<prop_blocks, 256>>>(n, inb, outb, pb, lap, mfw, out);
    }
}

// round 16
// speedup vs baseline: 1.2572x; 1.2572x over previous
#include <cuda_runtime.h>
#include <cuda_fp16.h>

#define NN   100000
#define EE   3200000
#define KORD 10
#define CC   64
#define FIN  512

// ---------------- scratch (static __device__, per allocation rules) -------------
// d_deg is zero at module load; k_scan3 re-zeroes it after use so every
// kernel_launch call sees it zeroed (invariant maintained across graph replays).
__device__ int     d_deg[NN];
__device__ int     d_rowptr[NN + 1];
__device__ int     d_cursor[NN];
__device__ int     d_blk[128];
__device__ float   d_dinv[NN];                   // deg>0 ? rsqrt(deg) : 1
__device__ float   d_wi[NN];                     // dinv^2
__device__ float   d_sdeg[NN];                   // sqrt(deg) or 1
__device__ int     d_srcs[EE];
__device__ __half2 d_Ph[KORD + 1][NN * (CC / 2)]; // all Chebyshev R_n = dinv*P_n (fp16)

// ---------------- CSR build ----------------------------------------------------
__global__ void k_count(const int* __restrict__ ei) {
    int t = blockIdx.x * blockDim.x + threadIdx.x;
    if (t < EE / 4) {
        int4 c4 = ((const int4*)(ei + EE))[t];
        atomicAdd(&d_deg[c4.x], 1);
        atomicAdd(&d_deg[c4.y], 1);
        atomicAdd(&d_deg[c4.z], 1);
        atomicAdd(&d_deg[c4.w], 1);
    }
}

__global__ void k_scan1() {
    __shared__ int sh[1024];
    int i = blockIdx.x * 1024 + threadIdx.x;
    int v = (i < NN) ? d_deg[i] : 0;
    sh[threadIdx.x] = v;
    __syncthreads();
    for (int off = 1; off < 1024; off <<= 1) {
        int t = (threadIdx.x >= off) ? sh[threadIdx.x - off] : 0;
        __syncthreads();
        sh[threadIdx.x] += t;
        __syncthreads();
    }
    if (i < NN) d_rowptr[i] = sh[threadIdx.x] - v;     // block-local exclusive
    if (threadIdx.x == 1023) d_blk[blockIdx.x] = sh[1023];
}

__global__ void k_scan2(int nblk) {                    // parallel exclusive scan, nblk<=128
    __shared__ int sh[128];
    int t = threadIdx.x;
    int v = (t < nblk) ? d_blk[t] : 0;
    sh[t] = v;
    __syncthreads();
    for (int off = 1; off < 128; off <<= 1) {
        int u = (t >= off) ? sh[t - off] : 0;
        __syncthreads();
        sh[t] += u;
        __syncthreads();
    }
    if (t < nblk) d_blk[t] = sh[t] - v;
}

__global__ void k_scan3() {
    int i = blockIdx.x * blockDim.x + threadIdx.x;
    if (i < NN) {
        int rp = d_rowptr[i] + d_blk[i >> 10];
        d_rowptr[i] = rp;
        d_cursor[i] = rp;
        int dg = d_deg[i];
        d_deg[i] = 0;                       // restore invariant for next launch
        d_dinv[i] = (dg > 0) ? rsqrtf((float)dg) : 1.0f;
        d_wi[i]   = (dg > 0) ? (1.0f / (float)dg) : 1.0f;
        d_sdeg[i] = (dg > 0) ? sqrtf((float)dg) : 1.0f;
    }
    if (i == 0) d_rowptr[NN] = EE;
}

__global__ void k_scatter(const int* __restrict__ ei) {
    int t = blockIdx.x * blockDim.x + threadIdx.x;
    if (t < EE / 4) {
        int4 r4 = ((const int4*)ei)[t];
        int4 c4 = ((const int4*)(ei + EE))[t];
        int p;
        p = atomicAdd(&d_cursor[c4.x], 1); d_srcs[p] = r4.x;
        p = atomicAdd(&d_cursor[c4.y], 1); d_srcs[p] = r4.y;
        p = atomicAdd(&d_cursor[c4.z], 1); d_srcs[p] = r4.z;
        p = atomicAdd(&d_cursor[c4.w], 1); d_srcs[p] = r4.w;
    }
}

// ---------------- GEMM: h = x @ W + b (fp32 float4, 128x64 tile, 8x4 micro) -----
// 256 threads as 16x16; each thread computes 8 rows x 4 cols. K-tile 32.
// Epilogue writes fp16 R0 = dinv*h.
__global__ __launch_bounds__(256) void k_gemm(const float* __restrict__ x,
                                              const float* __restrict__ W,
                                              const float* __restrict__ bias) {
    __shared__ float xsT[32][132];  // [k][m], padded
    __shared__ float Ws[32][64];    // [k][c]
    int tid = threadIdx.x;
    int m0  = blockIdx.x * 128;
    int ty  = tid >> 4, tx = tid & 15;

    float acc[8][4];
#pragma unroll
    for (int i = 0; i < 8; i++)
#pragma unroll
        for (int j = 0; j < 4; j++) acc[i][j] = 0.f;

    for (int k0 = 0; k0 < FIN; k0 += 32) {
#pragma unroll
        for (int it = 0; it < 4; ++it) {
            int idx = tid + it * 256;
            int row = idx >> 3, fc = idx & 7;
            float4 v = make_float4(0.f, 0.f, 0.f, 0.f);
            int gr = m0 + row;
            if (gr < NN) v = *(const float4*)(x + (long)gr * FIN + k0 + fc * 4);
            xsT[fc * 4 + 0][row] = v.x;
            xsT[fc * 4 + 1][row] = v.y;
            xsT[fc * 4 + 2][row] = v.z;
            xsT[fc * 4 + 3][row] = v.w;
        }
#pragma unroll
        for (int it = 0; it < 2; ++it) {
            int idx = tid + it * 256;
            int kr = idx >> 4, fc = idx & 15;
            *(float4*)&Ws[kr][fc * 4] = *(const float4*)(W + (k0 + kr) * CC + fc * 4);
        }
        __syncthreads();
#pragma unroll
        for (int kk = 0; kk < 32; ++kk) {
            float4 a0 = *(const float4*)&xsT[kk][ty * 8];
            float4 a1 = *(const float4*)&xsT[kk][ty * 8 + 4];
            float4 bb = *(const float4*)&Ws[kk][tx * 4];
            acc[0][0] += a0.x * bb.x; acc[0][1] += a0.x * bb.y; acc[0][2] += a0.x * bb.z; acc[0][3] += a0.x * bb.w;
            acc[1][0] += a0.y * bb.x; acc[1][1] += a0.y * bb.y; acc[1][2] += a0.y * bb.z; acc[1][3] += a0.y * bb.w;
            acc[2][0] += a0.z * bb.x; acc[2][1] += a0.z * bb.y; acc[2][2] += a0.z * bb.z; acc[2][3] += a0.z * bb.w;
            acc[3][0] += a0.w * bb.x; acc[3][1] += a0.w * bb.y; acc[3][2] += a0.w * bb.z; acc[3][3] += a0.w * bb.w;
            acc[4][0] += a1.x * bb.x; acc[4][1] += a1.x * bb.y; acc[4][2] += a1.x * bb.z; acc[4][3] += a1.x * bb.w;
            acc[5][0] += a1.y * bb.x; acc[5][1] += a1.y * bb.y; acc[5][2] += a1.y * bb.z; acc[5][3] += a1.y * bb.w;
            acc[6][0] += a1.z * bb.x; acc[6][1] += a1.z * bb.y; acc[6][2] += a1.z * bb.z; acc[6][3] += a1.z * bb.w;
            acc[7][0] += a1.w * bb.x; acc[7][1] += a1.w * bb.y; acc[7][2] += a1.w * bb.z; acc[7][3] += a1.w * bb.w;
        }
        __syncthreads();
    }

    float4 b4 = *(const float4*)(bias + tx * 4);
#pragma unroll
    for (int i = 0; i < 8; i++) {
        int row = m0 + ty * 8 + i;
        if (row < NN) {
            float h0 = acc[i][0] + b4.x;
            float h1 = acc[i][1] + b4.y;
            float h2 = acc[i][2] + b4.z;
            float h3 = acc[i][3] + b4.w;
            float dv = d_dinv[row];
            __half2* dst = d_Ph[0] + (long)row * (CC / 2) + tx * 2;
            dst[0] = __floats2half2_rn(dv * h0, dv * h1);   // R0 = dinv * h
            dst[1] = __floats2half2_rn(dv * h2, dv * h3);
        }
    }
}

// ---------------- propagate + recurrence (no combine) ---------------------------
// R_n stored fp16. s = sum_src R_{n-1}[src].
//   n==1: R_1 = w_i*s        (w_i = dinv^2)
//   n>=2: R_n = 2*w_i*s - R_{n-2}
// One warp per node; lane owns cols (2l,2l+1). 8-edge unroll, __ldcg gathers.
__device__ __forceinline__ float2 gat(const __half2* __restrict__ Pin, int s, int lane) {
    unsigned u = __ldcg((const unsigned*)(Pin + (long)s * (CC / 2) + lane));
    return __half22float2(*(const __half2*)&u);
}

__global__ __launch_bounds__(256) void k_prop(int n) {
    int gw   = (blockIdx.x * blockDim.x + threadIdx.x) >> 5;
    int lane = threadIdx.x & 31;
    if (gw >= NN) return;
    const __half2* __restrict__ Pin = d_Ph[n - 1];
    int beg = d_rowptr[gw], end = d_rowptr[gw + 1];

    float sx = 0.f, sy = 0.f;
    int p = beg;
    for (; p < end && (p & 3); ++p) {
        float2 f = gat(Pin, d_srcs[p], lane);
        sx += f.x; sy += f.y;
    }
    for (; p + 8 <= end; p += 8) {
        int4 a = *(const int4*)&d_srcs[p];
        int4 b = *(const int4*)&d_srcs[p + 4];
        float2 f0 = gat(Pin, a.x, lane);
        float2 f1 = gat(Pin, a.y, lane);
        float2 f2 = gat(Pin, a.z, lane);
        float2 f3 = gat(Pin, a.w, lane);
        float2 f4 = gat(Pin, b.x, lane);
        float2 f5 = gat(Pin, b.y, lane);
        float2 f6 = gat(Pin, b.z, lane);
        float2 f7 = gat(Pin, b.w, lane);
        sx += f0.x + f1.x + f2.x + f3.x + f4.x + f5.x + f6.x + f7.x;
        sy += f0.y + f1.y + f2.y + f3.y + f4.y + f5.y + f6.y + f7.y;
    }
    if (p + 4 <= end) {
        int4 a = *(const int4*)&d_srcs[p];
        float2 f0 = gat(Pin, a.x, lane);
        float2 f1 = gat(Pin, a.y, lane);
        float2 f2 = gat(Pin, a.z, lane);
        float2 f3 = gat(Pin, a.w, lane);
        sx += f0.x + f1.x + f2.x + f3.x;
        sy += f0.y + f1.y + f2.y + f3.y;
        p += 4;
    }
    for (; p < end; ++p) {
        float2 f = gat(Pin, d_srcs[p], lane);
        sx += f.x; sy += f.y;
    }

    float w = d_wi[gw];
    float px, py;
    if (n >= 2) {
        float2 q = __half22float2(d_Ph[n - 2][(long)gw * (CC / 2) + lane]);
        px = 2.f * w * sx - q.x;
        py = 2.f * w * sy - q.y;
    } else {
        px = w * sx;
        py = w * sy;
    }
    d_Ph[n][(long)gw * (CC / 2) + lane] = __floats2half2_rn(px, py);
}

// ---------------- final combine + log_softmax -----------------------------------
// a[c] = sdeg_i * sum_n coef_n * mfw[n][c] * R_n[i,c], coef_0=1, coef_n=lap[n-1]
__global__ __launch_bounds__(256) void k_combine(const float* __restrict__ lap,
                                                 const float* __restrict__ mfw,
                                                 float* __restrict__ out) {
    int gw   = (blockIdx.x * blockDim.x + threadIdx.x) >> 5;
    int lane = threadIdx.x & 31;
    if (gw >= NN) return;
    long base = (long)gw * (CC / 2) + lane;
    int  c2   = 2 * lane;

    float ax = 0.f, ay = 0.f;
#pragma unroll
    for (int n = 0; n <= KORD; n++) {
        float2 f = __half22float2(d_Ph[n][base]);
        float cn = (n == 0) ? 1.f : lap[n - 1];
        ax += cn * mfw[n * CC + c2]     * f.x;
        ay += cn * mfw[n * CC + c2 + 1] * f.y;
    }
    float sd = d_sdeg[gw];
    ax *= sd;
    ay *= sd;

    float m = fmaxf(ax, ay);
#pragma unroll
    for (int o = 16; o; o >>= 1) m = fmaxf(m, __shfl_xor_sync(0xffffffffu, m, o));
    float s = expf(ax - m) + expf(ay - m);
#pragma unroll
    for (int o = 16; o; o >>= 1) s += __shfl_xor_sync(0xffffffffu, s, o);
    float l = m + logf(s);
    *(float2*)(out + (long)gw * CC + c2) = make_float2(ax - l, ay - l);
}

// ---------------- launch --------------------------------------------------------
extern "C" void kernel_launch(void* const* d_in, const int* in_sizes, int n_in,
                              void* d_out, int out_size) {
    const float* x   = (const float*)d_in[0];
    const int*   ei  = (const int*)d_in[1];     // int32 (JAX default x64-disabled)
    const float* W   = (const float*)d_in[2];
    const float* b   = (const float*)d_in[3];
    const float* lap = (const float*)d_in[4];
    const float* mfw = (const float*)d_in[5];
    float*       out = (float*)d_out;

    (void)in_sizes; (void)n_in; (void)out_size;

    // d_deg is zeroed (module load on call 1; k_scan3 re-zeroes every call)
    k_count<<<(EE / 4 + 255) / 256, 256>>>(ei);
    int nblk = (NN + 1023) / 1024;   // 98
    k_scan1<<<nblk, 1024>>>();
    k_scan2<<<1, 128>>>(nblk);
    k_scan3<<<(NN + 255) / 256, 256>>>();
    k_scatter<<<(EE / 4 + 255) / 256, 256>>>(ei);

    k_gemm<<<(NN + 127) / 128, 256>>>(x, W, b);

    // warps = NN, 8 warps/block
    int prop_blocks = (NN + 7) / 8;
    for (int n = 1; n <= KORD; n++)
        k_prop<<<prop_blocks, 256>>>(n);

    k_combine<<<prop_blocks, 256>>>(lap, mfw, out);
}

// round 17
// speedup vs baseline: 1.4366x; 1.1427x over previous
#include <cuda_runtime.h>
#include <cuda_fp16.h>

#define NN   100000
#define EE   3200000
#define KORD 10
#define CC   64
#define FIN  512

// ---------------- scratch (static __device__, per allocation rules) -------------
// d_deg is zero at module load; k_scan3 re-zeroes it after use so every
// kernel_launch call sees it zeroed (invariant maintained across graph replays).
__device__ int     d_deg[NN];
__device__ int     d_rowptr[NN + 1];
__device__ int     d_cursor[NN];
__device__ int     d_blk[128];
__device__ float   d_dinv[NN];                   // deg>0 ? rsqrt(deg) : 1
__device__ float   d_wi[NN];                     // dinv^2
__device__ float   d_sdeg[NN];                   // sqrt(deg) or 1
__device__ int     d_srcs[EE];
__device__ __half2 d_Ph[KORD + 1][NN * (CC / 2)]; // all Chebyshev R_n = dinv*P_n (fp16)

// ---------------- CSR build ----------------------------------------------------
__global__ void k_count(const int* __restrict__ ei) {
    int t = blockIdx.x * blockDim.x + threadIdx.x;
    if (t < EE / 4) {
        int4 c4 = ((const int4*)(ei + EE))[t];
        atomicAdd(&d_deg[c4.x], 1);
        atomicAdd(&d_deg[c4.y], 1);
        atomicAdd(&d_deg[c4.z], 1);
        atomicAdd(&d_deg[c4.w], 1);
    }
}

__global__ void k_scan1() {
    __shared__ int sh[1024];
    int i = blockIdx.x * 1024 + threadIdx.x;
    int v = (i < NN) ? d_deg[i] : 0;
    sh[threadIdx.x] = v;
    __syncthreads();
    for (int off = 1; off < 1024; off <<= 1) {
        int t = (threadIdx.x >= off) ? sh[threadIdx.x - off] : 0;
        __syncthreads();
        sh[threadIdx.x] += t;
        __syncthreads();
    }
    if (i < NN) d_rowptr[i] = sh[threadIdx.x] - v;     // block-local exclusive
    if (threadIdx.x == 1023) d_blk[blockIdx.x] = sh[1023];
}

__global__ void k_scan2(int nblk) {                    // parallel exclusive scan, nblk<=128
    __shared__ int sh[128];
    int t = threadIdx.x;
    int v = (t < nblk) ? d_blk[t] : 0;
    sh[t] = v;
    __syncthreads();
    for (int off = 1; off < 128; off <<= 1) {
        int u = (t >= off) ? sh[t - off] : 0;
        __syncthreads();
        sh[t] += u;
        __syncthreads();
    }
    if (t < nblk) d_blk[t] = sh[t] - v;
}

__global__ void k_scan3() {
    int i = blockIdx.x * blockDim.x + threadIdx.x;
    if (i < NN) {
        int rp = d_rowptr[i] + d_blk[i >> 10];
        d_rowptr[i] = rp;
        d_cursor[i] = rp;
        int dg = d_deg[i];
        d_deg[i] = 0;                       // restore invariant for next launch
        d_dinv[i] = (dg > 0) ? rsqrtf((float)dg) : 1.0f;
        d_wi[i]   = (dg > 0) ? (1.0f / (float)dg) : 1.0f;
        d_sdeg[i] = (dg > 0) ? sqrtf((float)dg) : 1.0f;
    }
    if (i == 0) d_rowptr[NN] = EE;
}

__global__ void k_scatter(const int* __restrict__ ei) {
    int t = blockIdx.x * blockDim.x + threadIdx.x;
    if (t < EE / 4) {
        int4 r4 = ((const int4*)ei)[t];
        int4 c4 = ((const int4*)(ei + EE))[t];
        int p;
        p = atomicAdd(&d_cursor[c4.x], 1); d_srcs[p] = r4.x;
        p = atomicAdd(&d_cursor[c4.y], 1); d_srcs[p] = r4.y;
        p = atomicAdd(&d_cursor[c4.z], 1); d_srcs[p] = r4.z;
        p = atomicAdd(&d_cursor[c4.w], 1); d_srcs[p] = r4.w;
    }
}

// ---------------- tf32 helpers ---------------------------------------------------
__device__ __forceinline__ unsigned f2tf32(float f) {
    unsigned u;
    asm("cvt.rna.tf32.f32 %0, %1;" : "=r"(u) : "f"(f));
    return u;
}

__device__ __forceinline__ void mma_tf32(float& c0, float& c1, float& c2, float& c3,
                                         unsigned a0, unsigned a1, unsigned a2, unsigned a3,
                                         unsigned b0, unsigned b1) {
    asm volatile(
        "mma.sync.aligned.m16n8k8.row.col.f32.tf32.tf32.f32 "
        "{%0,%1,%2,%3}, {%4,%5,%6,%7}, {%8,%9}, {%0,%1,%2,%3};"
        : "+f"(c0), "+f"(c1), "+f"(c2), "+f"(c3)
        : "r"(a0), "r"(a1), "r"(a2), "r"(a3), "r"(b0), "r"(b1));
}

// ---------------- GEMM: h = x @ W + b  (tf32 mma.sync, 128x64 tile) --------------
// 256 threads = 8 warps as 4(m) x 2(n). Each warp: 32x32 out = 2 mtiles x 4 ntiles
// of m16n8k8. K-tile 16 in smem (2 k-subs of 8). Epilogue writes fp16 R0 = dinv*h.
#define XS_STRIDE 20
#define WS_STRIDE 72
__global__ __launch_bounds__(256) void k_gemm(const float* __restrict__ x,
                                              const float* __restrict__ W,
                                              const float* __restrict__ bias) {
    __shared__ unsigned xs[128 * XS_STRIDE];   // [m][k] tf32, padded
    __shared__ unsigned Ws[16 * WS_STRIDE];    // [k][c] tf32, padded
    int tid  = threadIdx.x;
    int lane = tid & 31;
    int wid  = tid >> 5;
    int wm   = wid & 3;          // warp row: 32 rows each
    int wn   = wid >> 2;         // warp col: 32 cols each
    int g    = lane >> 2;        // groupID 0..7
    int t4   = lane & 3;         // threadID_in_group 0..3
    int m0   = blockIdx.x * 128;

    float c[2][4][4];            // [mtile][ntile][frag]
#pragma unroll
    for (int i = 0; i < 2; i++)
#pragma unroll
        for (int j = 0; j < 4; j++)
#pragma unroll
            for (int r = 0; r < 4; r++) c[i][j][r] = 0.f;

    for (int k0 = 0; k0 < FIN; k0 += 16) {
        // load x tile: 128 rows x 16 k = 512 float4, 2 per thread
#pragma unroll
        for (int it = 0; it < 2; ++it) {
            int idx = tid + it * 256;
            int row = idx >> 2, f4 = idx & 3;
            float4 v = make_float4(0.f, 0.f, 0.f, 0.f);
            int gr = m0 + row;
            if (gr < NN) v = *(const float4*)(x + (long)gr * FIN + k0 + f4 * 4);
            unsigned* dst = &xs[row * XS_STRIDE + f4 * 4];
            dst[0] = f2tf32(v.x); dst[1] = f2tf32(v.y);
            dst[2] = f2tf32(v.z); dst[3] = f2tf32(v.w);
        }
        // load W tile: 16 k x 64 c = 256 float4, 1 per thread
        {
            int kr = tid >> 4, fc = tid & 15;
            float4 v = *(const float4*)(W + (long)(k0 + kr) * CC + fc * 4);
            unsigned* dst = &Ws[kr * WS_STRIDE + fc * 4];
            dst[0] = f2tf32(v.x); dst[1] = f2tf32(v.y);
            dst[2] = f2tf32(v.z); dst[3] = f2tf32(v.w);
        }
        __syncthreads();

#pragma unroll
        for (int ks = 0; ks < 16; ks += 8) {
            // A fragments for the 2 mtiles
            unsigned a[2][4];
#pragma unroll
            for (int mi = 0; mi < 2; mi++) {
                int rbase = wm * 32 + mi * 16 + g;
                a[mi][0] = xs[rbase * XS_STRIDE + ks + t4];
                a[mi][1] = xs[(rbase + 8) * XS_STRIDE + ks + t4];
                a[mi][2] = xs[rbase * XS_STRIDE + ks + t4 + 4];
                a[mi][3] = xs[(rbase + 8) * XS_STRIDE + ks + t4 + 4];
            }
            // B fragments for the 4 ntiles
            unsigned bf[4][2];
#pragma unroll
            for (int nj = 0; nj < 4; nj++) {
                int cbase = wn * 32 + nj * 8 + g;
                bf[nj][0] = Ws[(ks + t4) * WS_STRIDE + cbase];
                bf[nj][1] = Ws[(ks + t4 + 4) * WS_STRIDE + cbase];
            }
#pragma unroll
            for (int mi = 0; mi < 2; mi++)
#pragma unroll
                for (int nj = 0; nj < 4; nj++)
                    mma_tf32(c[mi][nj][0], c[mi][nj][1], c[mi][nj][2], c[mi][nj][3],
                             a[mi][0], a[mi][1], a[mi][2], a[mi][3],
                             bf[nj][0], bf[nj][1]);
        }
        __syncthreads();
    }

    // epilogue: h = c + bias; R0 = dinv * h (fp16). Thread (g,t4) owns cols
    // (2t4, 2t4+1) of each ntile at rows g and g+8 of each mtile.
#pragma unroll
    for (int nj = 0; nj < 4; nj++) {
        int col = wn * 32 + nj * 8 + 2 * t4;
        float b0 = bias[col], b1 = bias[col + 1];
#pragma unroll
        for (int mi = 0; mi < 2; mi++) {
            int r0 = m0 + wm * 32 + mi * 16 + g;
            if (r0 < NN) {
                float dv = d_dinv[r0];
                d_Ph[0][(long)r0 * (CC / 2) + (col >> 1)] =
                    __floats2half2_rn(dv * (c[mi][nj][0] + b0), dv * (c[mi][nj][1] + b1));
            }
            int r1 = r0 + 8;
            if (r1 < NN) {
                float dv = d_dinv[r1];
                d_Ph[0][(long)r1 * (CC / 2) + (col >> 1)] =
                    __floats2half2_rn(dv * (c[mi][nj][2] + b0), dv * (c[mi][nj][3] + b1));
            }
        }
    }
}

// ---------------- propagate + recurrence (no combine) ---------------------------
// R_n stored fp16. s = sum_src R_{n-1}[src].
//   n==1: R_1 = w_i*s        (w_i = dinv^2)
//   n>=2: R_n = 2*w_i*s - R_{n-2}
// One warp per node; lane owns cols (2l,2l+1). 8-edge unroll, __ldcg gathers.
__device__ __forceinline__ float2 gat(const __half2* __restrict__ Pin, int s, int lane) {
    unsigned u = __ldcg((const unsigned*)(Pin + (long)s * (CC / 2) + lane));
    return __half22float2(*(const __half2*)&u);
}

__global__ __launch_bounds__(256) void k_prop(int n) {
    int gw   = (blockIdx.x * blockDim.x + threadIdx.x) >> 5;
    int lane = threadIdx.x & 31;
    if (gw >= NN) return;
    const __half2* __restrict__ Pin = d_Ph[n - 1];
    int beg = d_rowptr[gw], end = d_rowptr[gw + 1];

    float sx = 0.f, sy = 0.f;
    int p = beg;
    for (; p < end && (p & 3); ++p) {
        float2 f = gat(Pin, d_srcs[p], lane);
        sx += f.x; sy += f.y;
    }
    for (; p + 8 <= end; p += 8) {
        int4 a = *(const int4*)&d_srcs[p];
        int4 b = *(const int4*)&d_srcs[p + 4];
        float2 f0 = gat(Pin, a.x, lane);
        float2 f1 = gat(Pin, a.y, lane);
        float2 f2 = gat(Pin, a.z, lane);
        float2 f3 = gat(Pin, a.w, lane);
        float2 f4 = gat(Pin, b.x, lane);
        float2 f5 = gat(Pin, b.y, lane);
        float2 f6 = gat(Pin, b.z, lane);
        float2 f7 = gat(Pin, b.w, lane);
        sx += f0.x + f1.x + f2.x + f3.x + f4.x + f5.x + f6.x + f7.x;
        sy += f0.y + f1.y + f2.y + f3.y + f4.y + f5.y + f6.y + f7.y;
    }
    if (p + 4 <= end) {
        int4 a = *(const int4*)&d_srcs[p];
        float2 f0 = gat(Pin, a.x, lane);
        float2 f1 = gat(Pin, a.y, lane);
        float2 f2 = gat(Pin, a.z, lane);
        float2 f3 = gat(Pin, a.w, lane);
        sx += f0.x + f1.x + f2.x + f3.x;
        sy += f0.y + f1.y + f2.y + f3.y;
        p += 4;
    }
    for (; p < end; ++p) {
        float2 f = gat(Pin, d_srcs[p], lane);
        sx += f.x; sy += f.y;
    }

    float w = d_wi[gw];
    float px, py;
    if (n >= 2) {
        float2 q = __half22float2(d_Ph[n - 2][(long)gw * (CC / 2) + lane]);
        px = 2.f * w * sx - q.x;
        py = 2.f * w * sy - q.y;
    } else {
        px = w * sx;
        py = w * sy;
    }
    d_Ph[n][(long)gw * (CC / 2) + lane] = __floats2half2_rn(px, py);
}

// ---------------- final combine + log_softmax -----------------------------------
// a[c] = sdeg_i * sum_n coef_n * mfw[n][c] * R_n[i,c], coef_0=1, coef_n=lap[n-1]
__global__ __launch_bounds__(256) void k_combine(const float* __restrict__ lap,
                                                 const float* __restrict__ mfw,
                                                 float* __restrict__ out) {
    int gw   = (blockIdx.x * blockDim.x + threadIdx.x) >> 5;
    int lane = threadIdx.x & 31;
    if (gw >= NN) return;
    long base = (long)gw * (CC / 2) + lane;
    int  c2   = 2 * lane;

    float ax = 0.f, ay = 0.f;
#pragma unroll
    for (int n = 0; n <= KORD; n++) {
        float2 f = __half22float2(d_Ph[n][base]);
        float cn = (n == 0) ? 1.f : lap[n - 1];
        ax += cn * mfw[n * CC + c2]     * f.x;
        ay += cn * mfw[n * CC + c2 + 1] * f.y;
    }
    float sd = d_sdeg[gw];
    ax *= sd;
    ay *= sd;

    float m = fmaxf(ax, ay);
#pragma unroll
    for (int o = 16; o; o >>= 1) m = fmaxf(m, __shfl_xor_sync(0xffffffffu, m, o));
    float s = expf(ax - m) + expf(ay - m);
#pragma unroll
    for (int o = 16; o; o >>= 1) s += __shfl_xor_sync(0xffffffffu, s, o);
    float l = m + logf(s);
    *(float2*)(out + (long)gw * CC + c2) = make_float2(ax - l, ay - l);
}

// ---------------- launch --------------------------------------------------------
extern "C" void kernel_launch(void* const* d_in, const int* in_sizes, int n_in,
                              void* d_out, int out_size) {
    const float* x   = (const float*)d_in[0];
    const int*   ei  = (const int*)d_in[1];     // int32 (JAX default x64-disabled)
    const float* W   = (const float*)d_in[2];
    const float* b   = (const float*)d_in[3];
    const float* lap = (const float*)d_in[4];
    const float* mfw = (const float*)d_in[5];
    float*       out = (float*)d_out;

    (void)in_sizes; (void)n_in; (void)out_size;

    // d_deg is zeroed (module load on call 1; k_scan3 re-zeroes every call)
    k_count<<<(EE / 4 + 255) / 256, 256>>>(ei);
    int nblk = (NN + 1023) / 1024;   // 98
    k_scan1<<<nblk, 1024>>>();
    k_scan2<<<1, 128>>>(nblk);
    k_scan3<<<(NN + 255) / 256, 256>>>();
    k_scatter<<<(EE / 4 + 255) / 256, 256>>>(ei);

    k_gemm<<<(NN + 127) / 128, 256>>>(x, W, b);

    // warps = NN, 8 warps/block
    int prop_blocks = (NN + 7) / 8;
    for (int n = 1; n <= KORD; n++)
        k_prop<<<prop_blocks, 256>>>(n);

    k_combine<<<prop_blocks, 256>>>(lap, mfw, out);
}